// round 13
// baseline (speedup 1.0000x reference)
#include <cuda_runtime.h>
#include <cuda_bf16.h>
#include <mma.h>
#include <cstdint>
#include <cstddef>

using namespace nvcuda;

#define DEPTH 18
#define NNODES ((1 << DEPTH) - 1)      // 262143
#define HDIM 128
#define LEAF_N (1 << (DEPTH - 1))      // 131072

// ================= device scratch (516 MiB total; largest object 192 MiB) =====
__device__ __align__(128) float g_h[(size_t)NNODES * HDIM];          // 128 MiB
__device__ __align__(128) float g_c[(size_t)NNODES * HDIM];          // 128 MiB
__device__ __align__(128) float g_fraw[(size_t)LEAF_N * HDIM];       // 64 MiB: raw fgate pre-act
__device__ __align__(128) float g_iouraw[(size_t)LEAF_N * 384];      // 192 MiB: raw iou pre-act
// weight images, bf16 pairs packed in uint32: [tile][n(128)][kpair(128)] (K=256)
// tiles 0-2: [W_iou;U_iou] n-tiles, tile 3: [W_f;U_f]
__device__ __align__(128) uint32_t g_Bhi[4 * 128 * 128];
__device__ __align__(128) uint32_t g_Blo[4 * 128 * 128];

__device__ __forceinline__ float sigmf(float x) { return 1.0f / (1.0f + __expf(-x)); }

// pure-integer bf16 hi/lo split (truncation): hi = top16(f), lo = top16(f - hi)
__device__ __forceinline__ void split2(float f0, float f1, uint32_t& hiw, uint32_t& low) {
    const uint32_t h0 = __float_as_uint(f0) & 0xFFFF0000u;
    const uint32_t h1 = __float_as_uint(f1) & 0xFFFF0000u;
    const uint32_t l0 = __float_as_uint(f0 - __uint_as_float(h0)) & 0xFFFF0000u;
    const uint32_t l1 = __float_as_uint(f1 - __uint_as_float(h1)) & 0xFFFF0000u;
    hiw = (h0 >> 16) | h1;
    low = (l0 >> 16) | l1;
}

// ================= static smem layout (bf16 elems, 40-elem padded rows) =====
#define PADK 40
#define E_ALO 5120
#define E_BHI 10240
#define E_BLO 15360
#define SM_ELEMS 20480            // 40 KB

// ================= one-time weight prep =================
__global__ void prep_weights(const float* __restrict__ Wiou, const float* __restrict__ Wf,
                             const float* __restrict__ Uiou, const float* __restrict__ Uf)
{
    const int idx = blockIdx.x * blockDim.x + threadIdx.x;
    if (idx >= 4 * 128 * 128) return;
    const int t = idx >> 14;
    const int n = (idx >> 7) & 127;
    const int kp = idx & 127;
    float v[2];
    #pragma unroll
    for (int e = 0; e < 2; e++) {
        const int k = kp * 2 + e;
        if (t < 3) {
            const int nn = t * 128 + n;
            v[e] = (k < 128) ? Wiou[k * 384 + nn] : Uiou[(k - 128) * 384 + nn];
        } else {
            v[e] = (k < 128) ? Wf[k * 128 + n] : Uf[(k - 128) * 128 + n];
        }
    }
    uint32_t hiw, low;
    split2(v[0], v[1], hiw, low);
    g_Bhi[idx] = hiw;
    g_Blo[idx] = low;
}

// ================= wmma GEMM core (64x64 warp tiles, 4 warps/CTA) ==========
// CTA = 128 rows x 128 cols, 4 warps as 2x2, each warp a 64x64 tile (Mf=Nf=4).
// K chunked by 32; chunk kc<4 sources pe (emb row), kc>=4 sources ph0(+ph1 summed).
// bf16-split: acc += A_hi*B_hi + A_hi*B_lo + A_lo*B_hi.
// Fragment loads per warp-ks: 16 for 48 MMAs (0.33 loads/MMA).
__device__ __forceinline__ void gemm_core(
    __nv_bfloat16* sm, int tid,
    const float* pe, const float* ph0, const float* ph1,   // per-thread A-row ptrs (nullable)
    int nkc,
    const uint32_t* bhi, const uint32_t* blo,              // weight tile base (128n x 128kp)
    float* __restrict__ C, int ldC, int m0, int colbase)
{
    const int wid = tid >> 5;
    const int wm = wid >> 1;      // 0..1  (64-row band)
    const int wn = wid & 1;       // 0..1  (64-col band)
    const int r = tid;            // A-staging row (1 thread per row)

    wmma::fragment<wmma::accumulator, 16, 16, 16, float> acc[4][4];
    #pragma unroll
    for (int mt = 0; mt < 4; mt++)
        #pragma unroll
        for (int nt = 0; nt < 4; nt++)
            wmma::fill_fragment(acc[mt][nt], 0.0f);

    for (int kc = 0; kc < nkc; kc++) {
        if (kc) __syncthreads();
        // ---- stage A chunk: thread r converts its full 32-float row ----
        {
            const float* p0;
            const float* p1 = nullptr;
            if (kc < 4) {
                p0 = pe ? pe + kc * 32 : nullptr;
            } else {
                p0 = ph0 ? ph0 + (kc - 4) * 32 : nullptr;
                p1 = ph1 ? ph1 + (kc - 4) * 32 : nullptr;
            }
            uint32_t* dhi = (uint32_t*)(sm + r * PADK);
            uint32_t* dlo = (uint32_t*)(sm + E_ALO + r * PADK);
            if (p0) {
                #pragma unroll
                for (int q = 0; q < 8; q++) {
                    float4 f = *(const float4*)(p0 + 4 * q);
                    if (p1) {
                        const float4 g = *(const float4*)(p1 + 4 * q);
                        f.x += g.x; f.y += g.y; f.z += g.z; f.w += g.w;
                    }
                    uint32_t h0, l0, h1, l1;
                    split2(f.x, f.y, h0, l0);
                    split2(f.z, f.w, h1, l1);
                    dhi[2 * q] = h0; dhi[2 * q + 1] = h1;
                    dlo[2 * q] = l0; dlo[2 * q + 1] = l1;
                }
            } else {
                #pragma unroll
                for (int q = 0; q < 16; q++) { dhi[q] = 0u; dlo[q] = 0u; }
            }
        }
        // ---- stage B chunk: 128 n-rows x 32 k (4 uint4/row/plane) ----
        {
            const uint4* shi = (const uint4*)bhi + kc * 4;
            const uint4* slo = (const uint4*)blo + kc * 4;
            #pragma unroll
            for (int i = tid; i < 512; i += 128) {
                const int nn = i >> 2;
                const int q = i & 3;
                *(uint4*)(sm + E_BHI + nn * PADK + q * 8) = shi[nn * 32 + q];
                *(uint4*)(sm + E_BLO + nn * PADK + q * 8) = slo[nn * 32 + q];
            }
        }
        __syncthreads();

        // ---- compute ----
        #pragma unroll
        for (int ks = 0; ks < 2; ks++) {
            wmma::fragment<wmma::matrix_a, 16, 16, 16, __nv_bfloat16, wmma::row_major> a_hi[4], a_lo[4];
            #pragma unroll
            for (int mt = 0; mt < 4; mt++) {
                const int arow = (wm * 64 + mt * 16) * PADK + ks * 16;
                wmma::load_matrix_sync(a_hi[mt], sm + arow, PADK);
                wmma::load_matrix_sync(a_lo[mt], sm + E_ALO + arow, PADK);
            }
            #pragma unroll
            for (int nt = 0; nt < 4; nt++) {
                const int brow = (wn * 64 + nt * 16) * PADK + ks * 16;
                wmma::fragment<wmma::matrix_b, 16, 16, 16, __nv_bfloat16, wmma::col_major> b_hi, b_lo;
                wmma::load_matrix_sync(b_hi, sm + E_BHI + brow, PADK);
                wmma::load_matrix_sync(b_lo, sm + E_BLO + brow, PADK);
                #pragma unroll
                for (int mt = 0; mt < 4; mt++) {
                    wmma::mma_sync(acc[mt][nt], a_hi[mt], b_hi, acc[mt][nt]);
                    wmma::mma_sync(acc[mt][nt], a_hi[mt], b_lo, acc[mt][nt]);
                    wmma::mma_sync(acc[mt][nt], a_lo[mt], b_hi, acc[mt][nt]);
                }
            }
        }
    }

    #pragma unroll
    for (int mt = 0; mt < 4; mt++)
        #pragma unroll
        for (int nt = 0; nt < 4; nt++) {
            const int row0 = m0 + wm * 64 + mt * 16;
            const int col0 = colbase + wn * 64 + nt * 16;
            wmma::store_matrix_sync(C + (size_t)row0 * ldC + col0, acc[mt][nt],
                                    ldC, wmma::mem_row_major);
        }
}

// leaves: g_iouraw[m] = emb(leaf m) @ W_iou (K=128); grid (3, 1024), 128 thr
__global__ __launch_bounds__(128, 2)
void leaf_gemm(const int* __restrict__ xids, const int* __restrict__ msk,
               const float* __restrict__ emb)
{
    __shared__ __align__(16) __nv_bfloat16 sm[SM_ELEMS];
    const int tid = threadIdx.x;
    const int bt = blockIdx.x;
    const int m0 = blockIdx.y * 128;

    const int node = (LEAF_N - 1) + m0 + tid;
    const int gid = xids[node] * msk[node];
    const float* pe = emb + (size_t)gid * HDIM;

    gemm_core(sm, tid, pe, nullptr, nullptr, 4,
              g_Bhi + bt * 16384, g_Blo + bt * 16384,
              g_iouraw, 384, m0, bt * 128);
}

// internal level: bx 0..2 = iou n-tiles (A=[emb(node)|h_l+h_r], K=256),
//                 bx 3    = fgate      (A=[emb(parent)|h_child], K=256)
__global__ __launch_bounds__(128, 2)
void level_gemm(const int* __restrict__ xids, const int* __restrict__ msk,
                const float* __restrict__ emb, int s0, int n)
{
    __shared__ __align__(16) __nv_bfloat16 sm[SM_ELEMS];
    const int tid = threadIdx.x;
    const int bx = blockIdx.x;
    const int m0 = blockIdx.y * 128;
    const int s1 = 2 * s0 + 1;

    const float* pe = nullptr;
    const float* ph0 = nullptr;
    const float* ph1 = nullptr;

    if (bx < 3) {
        if (m0 >= n) return;
        const int m = m0 + tid;
        if (m < n) {
            const int node = s0 + m;
            const int gid = xids[node] * msk[node];
            pe  = emb + (size_t)gid * HDIM;
            ph0 = g_h + (size_t)(s1 + 2 * m) * HDIM;
            ph1 = g_h + (size_t)(s1 + 2 * m + 1) * HDIM;
        }
        gemm_core(sm, tid, pe, ph0, ph1, 8,
                  g_Bhi + bx * 16384, g_Blo + bx * 16384,
                  g_iouraw, 384, m0, bx * 128);
    } else {
        const int ch = m0 + tid;
        if (ch < 2 * n) {
            const int parent = s0 + (ch >> 1);
            const int gid = xids[parent] * msk[parent];
            pe  = emb + (size_t)gid * HDIM;
            ph0 = g_h + (size_t)(s1 + ch) * HDIM;
        }
        gemm_core(sm, tid, pe, ph0, nullptr, 8,
                  g_Bhi + 3 * 16384, g_Blo + 3 * 16384,
                  g_fraw, 128, m0, 0);
    }
}

// ================= elementwise (biases folded here) =================
__global__ void leaf_update(const float* __restrict__ biou)
{
    const int idx = blockIdx.x * blockDim.x + threadIdx.x;
    if (idx >= LEAF_N * HDIM) return;
    const int m = idx >> 7;
    const int j = idx & 127;
    const int node = (LEAF_N - 1) + m;
    const float iv = g_iouraw[(size_t)m * 384 + j]       + biou[j];
    const float ov = g_iouraw[(size_t)m * 384 + 128 + j] + biou[128 + j];
    const float uv = g_iouraw[(size_t)m * 384 + 256 + j] + biou[256 + j];
    const float cv = sigmf(iv) * tanhf(uv);
    const float hv = sigmf(ov) * tanhf(cv);
    g_c[(size_t)node * HDIM + j] = cv;
    g_h[(size_t)node * HDIM + j] = hv;
}

__global__ void level_update(int s0, int n,
                             const float* __restrict__ biou, const float* __restrict__ bfv)
{
    const int idx = blockIdx.x * blockDim.x + threadIdx.x;
    if (idx >= n * HDIM) return;
    const int m = idx >> 7;
    const int j = idx & 127;
    const int node = s0 + m;
    const float bf = bfv[j];
    const float c0 = g_c[(size_t)(2 * node + 1) * HDIM + j];
    const float c1 = g_c[(size_t)(2 * node + 2) * HDIM + j];
    const float f0 = sigmf(g_fraw[(size_t)(2 * m) * HDIM + j] + bf);
    const float f1 = sigmf(g_fraw[(size_t)(2 * m + 1) * HDIM + j] + bf);
    const float fc = f0 * c0 + f1 * c1;
    const float iv = g_iouraw[(size_t)m * 384 + j]       + biou[j];
    const float ov = g_iouraw[(size_t)m * 384 + 128 + j] + biou[128 + j];
    const float uv = g_iouraw[(size_t)m * 384 + 256 + j] + biou[256 + j];
    const float cv = sigmf(iv) * tanhf(uv) + fc;
    const float hv = sigmf(ov) * tanhf(cv);
    g_c[(size_t)node * HDIM + j] = cv;
    g_h[(size_t)node * HDIM + j] = hv;
}

// ================= output projection =================
__global__ void out_gemm(const float* __restrict__ Wout,
                         const float* __restrict__ bout,
                         float* __restrict__ out)
{
    __shared__ float Ws[HDIM * 5];
    __shared__ float bs[5];
    const int tid = threadIdx.x;
    for (int i = tid; i < HDIM * 5; i += blockDim.x) Ws[i] = Wout[i];
    if (tid < 5) bs[tid] = bout[tid];
    __syncthreads();

    const int node = (blockIdx.x * blockDim.x + tid) >> 5;
    const int lane = tid & 31;
    if (node >= NNODES) return;

    const float* hp = g_h + (size_t)node * HDIM;
    float p[5] = {0.f, 0.f, 0.f, 0.f, 0.f};
    #pragma unroll
    for (int e = 0; e < 4; e++) {
        const int k = e * 32 + lane;
        const float x = hp[k];
        #pragma unroll
        for (int c = 0; c < 5; c++) p[c] += x * Ws[k * 5 + c];
    }
    #pragma unroll
    for (int off = 16; off > 0; off >>= 1)
        #pragma unroll
        for (int c = 0; c < 5; c++)
            p[c] += __shfl_xor_sync(0xffffffffu, p[c], off);

    if (lane == 0) {
        #pragma unroll
        for (int c = 0; c < 5; c++)
            out[(size_t)node * 5 + c] = p[c] + bs[c];
    }
}

// ================= launch =================
extern "C" void kernel_launch(void* const* d_in, const int* in_sizes, int n_in,
                              void* d_out, int out_size)
{
    const int*   x_ids = (const int*)d_in[0];
    const int*   mask  = (const int*)d_in[1];
    const float* emb   = (const float*)d_in[2];
    const float* W_iou = (const float*)d_in[3];
    const float* U_iou = (const float*)d_in[4];
    const float* b_iou = (const float*)d_in[5];
    const float* W_f   = (const float*)d_in[6];
    const float* U_f   = (const float*)d_in[7];
    const float* b_f   = (const float*)d_in[8];
    const float* W_out = (const float*)d_in[9];
    const float* b_out = (const float*)d_in[10];
    float* out = (float*)d_out;

    prep_weights<<<(4 * 128 * 128 + 255) / 256, 256>>>(W_iou, W_f, U_iou, U_f);

    {
        dim3 grid(3, LEAF_N / 128);
        leaf_gemm<<<grid, 128>>>(x_ids, mask, emb);
        leaf_update<<<(LEAF_N * HDIM + 255) / 256, 256>>>(b_iou);
    }

    for (int d = DEPTH - 2; d >= 0; --d) {
        const int n = 1 << d;
        const int s0 = n - 1;
        dim3 grid(4, (2 * n + 127) / 128);
        level_gemm<<<grid, 128>>>(x_ids, mask, emb, s0, n);
        level_update<<<(n * HDIM + 255) / 256, 256>>>(s0, n, b_iou, b_f);
    }

    out_gemm<<<(NNODES + 7) / 8, 256>>>(W_out, b_out, out);
}

// round 14
// speedup vs baseline: 1.0784x; 1.0784x over previous
#include <cuda_runtime.h>
#include <cuda_bf16.h>
#include <mma.h>
#include <cstdint>
#include <cstddef>

using namespace nvcuda;

#define DEPTH 18
#define NNODES ((1 << DEPTH) - 1)      // 262143
#define HDIM 128
#define LEAF_N (1 << (DEPTH - 1))      // 131072

// ================= device scratch (516 MiB total; largest object 192 MiB) =====
__device__ __align__(128) float g_h[(size_t)NNODES * HDIM];          // 128 MiB
__device__ __align__(128) float g_c[(size_t)NNODES * HDIM];          // 128 MiB
__device__ __align__(128) float g_fraw[(size_t)LEAF_N * HDIM];       // 64 MiB: raw fgate pre-act
__device__ __align__(128) float g_iouraw[(size_t)LEAF_N * 384];      // 192 MiB: raw iou pre-act
// weight images, bf16 pairs packed in uint32: [tile][n(128)][kpair(128)] (K=256)
// tiles 0-2: [W_iou;U_iou] n-tiles, tile 3: [W_f;U_f]
__device__ __align__(128) uint32_t g_Bhi[4 * 128 * 128];
__device__ __align__(128) uint32_t g_Blo[4 * 128 * 128];

__device__ __forceinline__ float sigmf(float x) { return 1.0f / (1.0f + __expf(-x)); }

// pure-integer bf16 hi/lo split (truncation): hi = top16(f), lo = top16(f - hi)
__device__ __forceinline__ void split2(float f0, float f1, uint32_t& hiw, uint32_t& low) {
    const uint32_t h0 = __float_as_uint(f0) & 0xFFFF0000u;
    const uint32_t h1 = __float_as_uint(f1) & 0xFFFF0000u;
    const uint32_t l0 = __float_as_uint(f0 - __uint_as_float(h0)) & 0xFFFF0000u;
    const uint32_t l1 = __float_as_uint(f1 - __uint_as_float(h1)) & 0xFFFF0000u;
    hiw = (h0 >> 16) | h1;
    low = (l0 >> 16) | l1;
}

// ================= smem layout per buffer (bf16 elems, 40-elem padded rows) ==
#define PADK 40
#define E_ALO 5120
#define E_BHI 10240
#define E_BLO 15360
#define SM_ELEMS 20480            // 40 KB per buffer; 2 buffers = 80 KB dynamic

// ================= one-time weight prep =================
__global__ void prep_weights(const float* __restrict__ Wiou, const float* __restrict__ Wf,
                             const float* __restrict__ Uiou, const float* __restrict__ Uf)
{
    const int idx = blockIdx.x * blockDim.x + threadIdx.x;
    if (idx >= 4 * 128 * 128) return;
    const int t = idx >> 14;
    const int n = (idx >> 7) & 127;
    const int kp = idx & 127;
    float v[2];
    #pragma unroll
    for (int e = 0; e < 2; e++) {
        const int k = kp * 2 + e;
        if (t < 3) {
            const int nn = t * 128 + n;
            v[e] = (k < 128) ? Wiou[k * 384 + nn] : Uiou[(k - 128) * 384 + nn];
        } else {
            v[e] = (k < 128) ? Wf[k * 128 + n] : Uf[(k - 128) * 128 + n];
        }
    }
    uint32_t hiw, low;
    split2(v[0], v[1], hiw, low);
    g_Bhi[idx] = hiw;
    g_Blo[idx] = low;
}

// ================= chunk staging (into one 40KB buffer) =================
__device__ __forceinline__ void stage_chunk(
    __nv_bfloat16* buf, int tid,
    const float* pe, const float* ph0, const float* ph1, int kc,
    const uint32_t* bhi, const uint32_t* blo)
{
    const int r = tid >> 1;
    const int sel = tid & 1;
    // ---- A: 2 threads per row, 16 floats each, f32 -> bf16 hi/lo ----
    {
        const float* p0;
        const float* p1 = nullptr;
        if (kc < 4) {
            p0 = pe ? pe + kc * 32 + sel * 16 : nullptr;
        } else {
            p0 = ph0 ? ph0 + (kc - 4) * 32 + sel * 16 : nullptr;
            p1 = ph1 ? ph1 + (kc - 4) * 32 + sel * 16 : nullptr;
        }
        uint32_t* dhi = (uint32_t*)(buf + r * PADK) + sel * 8;
        uint32_t* dlo = (uint32_t*)(buf + E_ALO + r * PADK) + sel * 8;
        if (p0) {
            #pragma unroll
            for (int q = 0; q < 4; q++) {
                float4 f = *(const float4*)(p0 + 4 * q);
                if (p1) {
                    const float4 g = *(const float4*)(p1 + 4 * q);
                    f.x += g.x; f.y += g.y; f.z += g.z; f.w += g.w;
                }
                uint32_t h0, l0, h1, l1;
                split2(f.x, f.y, h0, l0);
                split2(f.z, f.w, h1, l1);
                dhi[2 * q] = h0; dhi[2 * q + 1] = h1;
                dlo[2 * q] = l0; dlo[2 * q + 1] = l1;
            }
        } else {
            #pragma unroll
            for (int q = 0; q < 8; q++) { dhi[q] = 0u; dlo[q] = 0u; }
        }
    }
    // ---- B: 128 n-rows x 32 k (4 uint4/row/plane) ----
    {
        const uint4* shi = (const uint4*)bhi + kc * 4;
        const uint4* slo = (const uint4*)blo + kc * 4;
        #pragma unroll
        for (int i = tid; i < 512; i += 256) {
            const int nn = i >> 2;
            const int q = i & 3;
            *(uint4*)(buf + E_BHI + nn * PADK + q * 8) = shi[nn * 32 + q];
            *(uint4*)(buf + E_BLO + nn * PADK + q * 8) = slo[nn * 32 + q];
        }
    }
}

// ================= wmma GEMM core (double-buffered pipeline) ===============
// CTA = 128x128 tile, 8 warps (wm 0..3 = 32 rows, wn 0..1 = 64 cols).
// Pipeline: stage(kc+1) -> other buffer overlaps compute(kc); 1 barrier/chunk.
// bf16-split: acc += A_hi*B_hi + A_hi*B_lo + A_lo*B_hi (fragments register-cached).
__device__ __forceinline__ void gemm_core(
    __nv_bfloat16* sm, int tid,
    const float* pe, const float* ph0, const float* ph1,   // per-thread row ptrs (nullable)
    int nkc,
    const uint32_t* bhi, const uint32_t* blo,              // weight tile base (128n x 128kp)
    float* __restrict__ C, int ldC, int m0, int colbase)
{
    const int wid = tid >> 5;
    const int wm = wid >> 1;
    const int wn = wid & 1;

    wmma::fragment<wmma::accumulator, 16, 16, 16, float> acc[2][4];
    #pragma unroll
    for (int mt = 0; mt < 2; mt++)
        #pragma unroll
        for (int nt = 0; nt < 4; nt++)
            wmma::fill_fragment(acc[mt][nt], 0.0f);

    stage_chunk(sm, tid, pe, ph0, ph1, 0, bhi, blo);
    __syncthreads();

    for (int kc = 0; kc < nkc; kc++) {
        __nv_bfloat16* cur = sm + (kc & 1) * SM_ELEMS;
        if (kc + 1 < nkc)
            stage_chunk(sm + ((kc + 1) & 1) * SM_ELEMS, tid, pe, ph0, ph1, kc + 1, bhi, blo);

        #pragma unroll
        for (int ks = 0; ks < 2; ks++) {
            wmma::fragment<wmma::matrix_a, 16, 16, 16, __nv_bfloat16, wmma::row_major> a_hi[2], a_lo[2];
            #pragma unroll
            for (int mt = 0; mt < 2; mt++) {
                const int arow = (wm * 32 + mt * 16) * PADK + ks * 16;
                wmma::load_matrix_sync(a_hi[mt], cur + arow, PADK);
                wmma::load_matrix_sync(a_lo[mt], cur + E_ALO + arow, PADK);
            }
            #pragma unroll
            for (int nt = 0; nt < 4; nt++) {
                const int brow = (wn * 64 + nt * 16) * PADK + ks * 16;
                wmma::fragment<wmma::matrix_b, 16, 16, 16, __nv_bfloat16, wmma::col_major> b_hi, b_lo;
                wmma::load_matrix_sync(b_hi, cur + E_BHI + brow, PADK);
                wmma::load_matrix_sync(b_lo, cur + E_BLO + brow, PADK);
                #pragma unroll
                for (int mt = 0; mt < 2; mt++) {
                    wmma::mma_sync(acc[mt][nt], a_hi[mt], b_hi, acc[mt][nt]);
                    wmma::mma_sync(acc[mt][nt], a_hi[mt], b_lo, acc[mt][nt]);
                    wmma::mma_sync(acc[mt][nt], a_lo[mt], b_hi, acc[mt][nt]);
                }
            }
        }
        __syncthreads();
    }

    #pragma unroll
    for (int mt = 0; mt < 2; mt++)
        #pragma unroll
        for (int nt = 0; nt < 4; nt++) {
            const int row0 = m0 + wm * 32 + mt * 16;
            const int col0 = colbase + wn * 64 + nt * 16;
            wmma::store_matrix_sync(C + (size_t)row0 * ldC + col0, acc[mt][nt],
                                    ldC, wmma::mem_row_major);
        }
}

// leaves: g_iouraw[m] = emb(leaf m) @ W_iou (K=128); grid (3, 1024)
__global__ __launch_bounds__(256, 2)
void leaf_gemm(const int* __restrict__ xids, const int* __restrict__ msk,
               const float* __restrict__ emb)
{
    extern __shared__ __align__(16) __nv_bfloat16 sm[];
    const int tid = threadIdx.x;
    const int bt = blockIdx.x;
    const int m0 = blockIdx.y * 128;

    const int node = (LEAF_N - 1) + m0 + (tid >> 1);
    const int gid = xids[node] * msk[node];
    const float* pe = emb + (size_t)gid * HDIM;

    gemm_core(sm, tid, pe, nullptr, nullptr, 4,
              g_Bhi + bt * 16384, g_Blo + bt * 16384,
              g_iouraw, 384, m0, bt * 128);
}

// internal level: bx 0..2 = iou n-tiles (A=[emb(node)|h_l+h_r], K=256),
//                 bx 3    = fgate      (A=[emb(parent)|h_child], K=256)
__global__ __launch_bounds__(256, 2)
void level_gemm(const int* __restrict__ xids, const int* __restrict__ msk,
                const float* __restrict__ emb, int s0, int n)
{
    extern __shared__ __align__(16) __nv_bfloat16 sm[];
    const int tid = threadIdx.x;
    const int bx = blockIdx.x;
    const int m0 = blockIdx.y * 128;
    const int s1 = 2 * s0 + 1;
    const int r = tid >> 1;

    const float* pe = nullptr;
    const float* ph0 = nullptr;
    const float* ph1 = nullptr;

    if (bx < 3) {
        if (m0 >= n) return;
        const int m = m0 + r;
        if (m < n) {
            const int node = s0 + m;
            const int gid = xids[node] * msk[node];
            pe  = emb + (size_t)gid * HDIM;
            ph0 = g_h + (size_t)(s1 + 2 * m) * HDIM;
            ph1 = g_h + (size_t)(s1 + 2 * m + 1) * HDIM;
        }
        gemm_core(sm, tid, pe, ph0, ph1, 8,
                  g_Bhi + bx * 16384, g_Blo + bx * 16384,
                  g_iouraw, 384, m0, bx * 128);
    } else {
        const int ch = m0 + r;
        if (ch < 2 * n) {
            const int parent = s0 + (ch >> 1);
            const int gid = xids[parent] * msk[parent];
            pe  = emb + (size_t)gid * HDIM;
            ph0 = g_h + (size_t)(s1 + ch) * HDIM;
        }
        gemm_core(sm, tid, pe, ph0, nullptr, 8,
                  g_Bhi + 3 * 16384, g_Blo + 3 * 16384,
                  g_fraw, 128, m0, 0);
    }
}

// ================= elementwise (biases folded here) =================
__global__ void leaf_update(const float* __restrict__ biou)
{
    const int idx = blockIdx.x * blockDim.x + threadIdx.x;
    if (idx >= LEAF_N * HDIM) return;
    const int m = idx >> 7;
    const int j = idx & 127;
    const int node = (LEAF_N - 1) + m;
    const float iv = g_iouraw[(size_t)m * 384 + j]       + biou[j];
    const float ov = g_iouraw[(size_t)m * 384 + 128 + j] + biou[128 + j];
    const float uv = g_iouraw[(size_t)m * 384 + 256 + j] + biou[256 + j];
    const float cv = sigmf(iv) * tanhf(uv);
    const float hv = sigmf(ov) * tanhf(cv);
    g_c[(size_t)node * HDIM + j] = cv;
    g_h[(size_t)node * HDIM + j] = hv;
}

__global__ void level_update(int s0, int n,
                             const float* __restrict__ biou, const float* __restrict__ bfv)
{
    const int idx = blockIdx.x * blockDim.x + threadIdx.x;
    if (idx >= n * HDIM) return;
    const int m = idx >> 7;
    const int j = idx & 127;
    const int node = s0 + m;
    const float bf = bfv[j];
    const float c0 = g_c[(size_t)(2 * node + 1) * HDIM + j];
    const float c1 = g_c[(size_t)(2 * node + 2) * HDIM + j];
    const float f0 = sigmf(g_fraw[(size_t)(2 * m) * HDIM + j] + bf);
    const float f1 = sigmf(g_fraw[(size_t)(2 * m + 1) * HDIM + j] + bf);
    const float fc = f0 * c0 + f1 * c1;
    const float iv = g_iouraw[(size_t)m * 384 + j]       + biou[j];
    const float ov = g_iouraw[(size_t)m * 384 + 128 + j] + biou[128 + j];
    const float uv = g_iouraw[(size_t)m * 384 + 256 + j] + biou[256 + j];
    const float cv = sigmf(iv) * tanhf(uv) + fc;
    const float hv = sigmf(ov) * tanhf(cv);
    g_c[(size_t)node * HDIM + j] = cv;
    g_h[(size_t)node * HDIM + j] = hv;
}

// ================= output projection =================
__global__ void out_gemm(const float* __restrict__ Wout,
                         const float* __restrict__ bout,
                         float* __restrict__ out)
{
    __shared__ float Ws[HDIM * 5];
    __shared__ float bs[5];
    const int tid = threadIdx.x;
    for (int i = tid; i < HDIM * 5; i += blockDim.x) Ws[i] = Wout[i];
    if (tid < 5) bs[tid] = bout[tid];
    __syncthreads();

    const int node = (blockIdx.x * blockDim.x + tid) >> 5;
    const int lane = tid & 31;
    if (node >= NNODES) return;

    const float* hp = g_h + (size_t)node * HDIM;
    float p[5] = {0.f, 0.f, 0.f, 0.f, 0.f};
    #pragma unroll
    for (int e = 0; e < 4; e++) {
        const int k = e * 32 + lane;
        const float x = hp[k];
        #pragma unroll
        for (int c = 0; c < 5; c++) p[c] += x * Ws[k * 5 + c];
    }
    #pragma unroll
    for (int off = 16; off > 0; off >>= 1)
        #pragma unroll
        for (int c = 0; c < 5; c++)
            p[c] += __shfl_xor_sync(0xffffffffu, p[c], off);

    if (lane == 0) {
        #pragma unroll
        for (int c = 0; c < 5; c++)
            out[(size_t)node * 5 + c] = p[c] + bs[c];
    }
}

// ================= launch =================
#define SMEM_DYN (2 * SM_ELEMS * (int)sizeof(__nv_bfloat16))   // 81920 B

extern "C" void kernel_launch(void* const* d_in, const int* in_sizes, int n_in,
                              void* d_out, int out_size)
{
    const int*   x_ids = (const int*)d_in[0];
    const int*   mask  = (const int*)d_in[1];
    const float* emb   = (const float*)d_in[2];
    const float* W_iou = (const float*)d_in[3];
    const float* U_iou = (const float*)d_in[4];
    const float* b_iou = (const float*)d_in[5];
    const float* W_f   = (const float*)d_in[6];
    const float* U_f   = (const float*)d_in[7];
    const float* b_f   = (const float*)d_in[8];
    const float* W_out = (const float*)d_in[9];
    const float* b_out = (const float*)d_in[10];
    float* out = (float*)d_out;

    cudaFuncSetAttribute(leaf_gemm, cudaFuncAttributeMaxDynamicSharedMemorySize, SMEM_DYN);
    cudaFuncSetAttribute(level_gemm, cudaFuncAttributeMaxDynamicSharedMemorySize, SMEM_DYN);

    prep_weights<<<(4 * 128 * 128 + 255) / 256, 256>>>(W_iou, W_f, U_iou, U_f);

    {
        dim3 grid(3, LEAF_N / 128);
        leaf_gemm<<<grid, 256, SMEM_DYN>>>(x_ids, mask, emb);
        leaf_update<<<(LEAF_N * HDIM + 255) / 256, 256>>>(b_iou);
    }

    for (int d = DEPTH - 2; d >= 0; --d) {
        const int n = 1 << d;
        const int s0 = n - 1;
        dim3 grid(4, (2 * n + 127) / 128);
        level_gemm<<<grid, 256, SMEM_DYN>>>(x_ids, mask, emb, s0, n);
        level_update<<<(n * HDIM + 255) / 256, 256>>>(s0, n, b_iou, b_f);
    }

    out_gemm<<<(NNODES + 7) / 8, 256>>>(W_out, b_out, out);
}

// round 15
// speedup vs baseline: 1.5683x; 1.4543x over previous
#include <cuda_runtime.h>
#include <cuda_bf16.h>
#include <mma.h>
#include <cstdint>
#include <cstddef>

using namespace nvcuda;

#define DEPTH 18
#define NNODES ((1 << DEPTH) - 1)      // 262143
#define HDIM 128
#define LEAF_N (1 << (DEPTH - 1))      // 131072
#define VOCAB 32000

// ================= device scratch (~482 MiB; largest object 128 MiB) =========
__device__ __align__(128) float g_h[(size_t)NNODES * HDIM];            // 128 MiB
__device__ __align__(128) float g_c[(size_t)NNODES * HDIM];            // 128 MiB
__device__ __align__(128) float g_fraw[(size_t)LEAF_N * HDIM];         // 64 MiB (max 2n = 131072)
__device__ __align__(128) float g_iouraw[(size_t)(LEAF_N / 2) * 384];  // 96 MiB (max n = 65536)
__device__ __align__(128) float g_tbl[(size_t)VOCAB * 512];            // 65.5 MiB: emb@[Wiou|Wf]+bias
// weight images, bf16 pairs packed in uint32: [tile][n(128)][kpair(64)] (K=128)
// tiles 0-2: Wiou n-tiles, 3: Wf, 4-6: Uiou n-tiles, 7: Uf
__device__ __align__(128) uint32_t g_Bhi[8 * 128 * 64];
__device__ __align__(128) uint32_t g_Blo[8 * 128 * 64];
__device__ __align__(128) float g_bcat[512];

__device__ __forceinline__ float sigmf(float x) { return 1.0f / (1.0f + __expf(-x)); }

// pure-integer bf16 hi/lo split (truncation): hi = top16(f), lo = top16(f - hi)
__device__ __forceinline__ void split2(float f0, float f1, uint32_t& hiw, uint32_t& low) {
    const uint32_t h0 = __float_as_uint(f0) & 0xFFFF0000u;
    const uint32_t h1 = __float_as_uint(f1) & 0xFFFF0000u;
    const uint32_t l0 = __float_as_uint(f0 - __uint_as_float(h0)) & 0xFFFF0000u;
    const uint32_t l1 = __float_as_uint(f1 - __uint_as_float(h1)) & 0xFFFF0000u;
    hiw = (h0 >> 16) | h1;
    low = (l0 >> 16) | l1;
}

// ================= smem layout per buffer (bf16 elems, 40-elem padded rows) ==
#define PADK 40
#define E_ALO 5120
#define E_BHI 10240
#define E_BLO 15360
#define SM_ELEMS 20480            // 40 KB per buffer; 2 buffers = 80 KB dynamic
#define SMEM_DYN (2 * SM_ELEMS * (int)sizeof(__nv_bfloat16))   // 81920 B

// ================= one-time weight prep =================
__global__ void prep_weights(const float* __restrict__ Wiou, const float* __restrict__ Wf,
                             const float* __restrict__ Uiou, const float* __restrict__ Uf,
                             const float* __restrict__ biou, const float* __restrict__ bf)
{
    const int idx = blockIdx.x * blockDim.x + threadIdx.x;
    if (idx < 512) g_bcat[idx] = (idx < 384) ? biou[idx] : bf[idx - 384];
    if (idx >= 8 * 128 * 64) return;
    const int t = idx >> 13;
    const int n = (idx >> 6) & 127;
    const int kp = idx & 63;
    float v[2];
    #pragma unroll
    for (int e = 0; e < 2; e++) {
        const int k = kp * 2 + e;
        if (t < 3)      v[e] = Wiou[k * 384 + t * 128 + n];
        else if (t == 3) v[e] = Wf[k * 128 + n];
        else if (t < 7)  v[e] = Uiou[k * 384 + (t - 4) * 128 + n];
        else             v[e] = Uf[k * 128 + n];
    }
    uint32_t hiw, low;
    split2(v[0], v[1], hiw, low);
    g_Bhi[idx] = hiw;
    g_Blo[idx] = low;
}

// ================= chunk staging (into one 40KB buffer) =================
// A: p0 (+ optional p1, summed) are 128-float row bases; chunk kc reads [kc*32, kc*32+32)
// B: tile is [128n][64kp] uint32 (16 uint4 per row); chunk kc -> uint4 cols [kc*4, kc*4+4)
__device__ __forceinline__ void stage_chunk(
    __nv_bfloat16* buf, int tid,
    const float* p0, const float* p1, int kc,
    const uint32_t* bhi, const uint32_t* blo)
{
    const int r = tid >> 1;
    const int sel = tid & 1;
    {
        const float* q0 = p0 ? p0 + kc * 32 + sel * 16 : nullptr;
        const float* q1 = p1 ? p1 + kc * 32 + sel * 16 : nullptr;
        uint32_t* dhi = (uint32_t*)(buf + r * PADK) + sel * 8;
        uint32_t* dlo = (uint32_t*)(buf + E_ALO + r * PADK) + sel * 8;
        if (q0) {
            #pragma unroll
            for (int q = 0; q < 4; q++) {
                float4 f = *(const float4*)(q0 + 4 * q);
                if (q1) {
                    const float4 g = *(const float4*)(q1 + 4 * q);
                    f.x += g.x; f.y += g.y; f.z += g.z; f.w += g.w;
                }
                uint32_t h0, l0, h1, l1;
                split2(f.x, f.y, h0, l0);
                split2(f.z, f.w, h1, l1);
                dhi[2 * q] = h0; dhi[2 * q + 1] = h1;
                dlo[2 * q] = l0; dlo[2 * q + 1] = l1;
            }
        } else {
            #pragma unroll
            for (int q = 0; q < 8; q++) { dhi[q] = 0u; dlo[q] = 0u; }
        }
    }
    {
        const uint4* shi = (const uint4*)bhi + kc * 4;
        const uint4* slo = (const uint4*)blo + kc * 4;
        #pragma unroll
        for (int i = tid; i < 512; i += 256) {
            const int nn = i >> 2;
            const int q = i & 3;
            *(uint4*)(buf + E_BHI + nn * PADK + q * 8) = shi[nn * 16 + q];
            *(uint4*)(buf + E_BLO + nn * PADK + q * 8) = slo[nn * 16 + q];
        }
    }
}

// ================= wmma GEMM core (K=128, double-buffered) =================
// CTA = 128x128 tile, 8 warps (wm 0..3 = 32 rows, wn 0..1 = 64 cols).
// bf16-split: acc += A_hi*B_hi + A_hi*B_lo + A_lo*B_hi (fragments register-cached).
__device__ __forceinline__ void gemm_core(
    __nv_bfloat16* sm, int tid,
    const float* p0, const float* p1,                      // per-thread A-row ptrs (nullable)
    const uint32_t* bhi, const uint32_t* blo,              // weight tile base (128n x 64kp)
    float* __restrict__ C, int ldC, int m0, int colbase,
    const float* __restrict__ bias)                        // nullable, indexed by global col
{
    const int wid = tid >> 5;
    const int wm = wid >> 1;
    const int wn = wid & 1;

    wmma::fragment<wmma::accumulator, 16, 16, 16, float> acc[2][4];
    #pragma unroll
    for (int mt = 0; mt < 2; mt++)
        #pragma unroll
        for (int nt = 0; nt < 4; nt++)
            wmma::fill_fragment(acc[mt][nt], 0.0f);

    stage_chunk(sm, tid, p0, p1, 0, bhi, blo);
    __syncthreads();

    for (int kc = 0; kc < 4; kc++) {
        __nv_bfloat16* cur = sm + (kc & 1) * SM_ELEMS;
        if (kc + 1 < 4)
            stage_chunk(sm + ((kc + 1) & 1) * SM_ELEMS, tid, p0, p1, kc + 1, bhi, blo);

        #pragma unroll
        for (int ks = 0; ks < 2; ks++) {
            wmma::fragment<wmma::matrix_a, 16, 16, 16, __nv_bfloat16, wmma::row_major> a_hi[2], a_lo[2];
            #pragma unroll
            for (int mt = 0; mt < 2; mt++) {
                const int arow = (wm * 32 + mt * 16) * PADK + ks * 16;
                wmma::load_matrix_sync(a_hi[mt], cur + arow, PADK);
                wmma::load_matrix_sync(a_lo[mt], cur + E_ALO + arow, PADK);
            }
            #pragma unroll
            for (int nt = 0; nt < 4; nt++) {
                const int brow = (wn * 64 + nt * 16) * PADK + ks * 16;
                wmma::fragment<wmma::matrix_b, 16, 16, 16, __nv_bfloat16, wmma::col_major> b_hi, b_lo;
                wmma::load_matrix_sync(b_hi, cur + E_BHI + brow, PADK);
                wmma::load_matrix_sync(b_lo, cur + E_BLO + brow, PADK);
                #pragma unroll
                for (int mt = 0; mt < 2; mt++) {
                    wmma::mma_sync(acc[mt][nt], a_hi[mt], b_hi, acc[mt][nt]);
                    wmma::mma_sync(acc[mt][nt], a_hi[mt], b_lo, acc[mt][nt]);
                    wmma::mma_sync(acc[mt][nt], a_lo[mt], b_hi, acc[mt][nt]);
                }
            }
        }
        __syncthreads();
    }

    const int lane = tid & 31;
    #pragma unroll
    for (int mt = 0; mt < 2; mt++)
        #pragma unroll
        for (int nt = 0; nt < 4; nt++) {
            const int row0 = m0 + wm * 32 + mt * 16;
            const int col0 = colbase + wn * 64 + nt * 16;
            if (bias) {
                #pragma unroll
                for (int e = 0; e < acc[mt][nt].num_elements; e++) {
                    // fp32 acc m16n16: col = (e%2) + (e/4)*8 + (lane%4)*2 ; add bias by col
                    const int cc = (e & 1) + ((e >> 2) << 3) + ((lane & 3) << 1);
                    acc[mt][nt].x[e] += bias[col0 + cc];
                }
            }
            wmma::store_matrix_sync(C + (size_t)row0 * ldC + col0, acc[mt][nt],
                                    ldC, wmma::mem_row_major);
        }
}

// proj table: g_tbl[v] = emb_table[v] @ [Wiou|Wf] + bcat ; grid (4, 250)
__global__ __launch_bounds__(256, 2)
void proj_gemm(const float* __restrict__ emb)
{
    extern __shared__ __align__(16) __nv_bfloat16 sm[];
    const int tid = threadIdx.x;
    const int bt = blockIdx.x;
    const int m0 = blockIdx.y * 128;
    const int row = m0 + (tid >> 1);
    const float* p0 = (row < VOCAB) ? emb + (size_t)row * HDIM : nullptr;
    gemm_core(sm, tid, p0, nullptr,
              g_Bhi + bt * 8192, g_Blo + bt * 8192,
              g_tbl, 512, m0, bt * 128, g_bcat);
}

// internal level (K=128): bx 0..2 = iou n-tiles (A = h_l + h_r),
//                         bx 3    = fgate      (A = h_child)
__global__ __launch_bounds__(256, 2)
void level_gemm(int s0, int n)
{
    extern __shared__ __align__(16) __nv_bfloat16 sm[];
    const int tid = threadIdx.x;
    const int bx = blockIdx.x;
    const int m0 = blockIdx.y * 128;
    const int s1 = 2 * s0 + 1;
    const int r = tid >> 1;

    if (bx < 3) {
        if (m0 >= n) return;
        const int m = m0 + r;
        const float* p0 = nullptr;
        const float* p1 = nullptr;
        if (m < n) {
            p0 = g_h + (size_t)(s1 + 2 * m) * HDIM;
            p1 = g_h + (size_t)(s1 + 2 * m + 1) * HDIM;
        }
        gemm_core(sm, tid, p0, p1,
                  g_Bhi + (4 + bx) * 8192, g_Blo + (4 + bx) * 8192,
                  g_iouraw, 384, m0, bx * 128, nullptr);
    } else {
        const int ch = m0 + r;
        const float* p0 = (ch < 2 * n) ? g_h + (size_t)(s1 + ch) * HDIM : nullptr;
        gemm_core(sm, tid, p0, nullptr,
                  g_Bhi + 7 * 8192, g_Blo + 7 * 8192,
                  g_fraw, 128, m0, 0, nullptr);
    }
}

// ================= elementwise =================
__global__ void leaf_update(const int* __restrict__ xids, const int* __restrict__ msk)
{
    const int idx = blockIdx.x * blockDim.x + threadIdx.x;
    if (idx >= LEAF_N * HDIM) return;
    const int m = idx >> 7;
    const int j = idx & 127;
    const int node = (LEAF_N - 1) + m;
    const int gid = xids[node] * msk[node];
    const float* t = g_tbl + (size_t)gid * 512;
    const float cv = sigmf(t[j]) * tanhf(t[256 + j]);
    const float hv = sigmf(t[128 + j]) * tanhf(cv);
    g_c[(size_t)node * HDIM + j] = cv;
    g_h[(size_t)node * HDIM + j] = hv;
}

__global__ void level_update(const int* __restrict__ xids, const int* __restrict__ msk,
                             int s0, int n)
{
    const int idx = blockIdx.x * blockDim.x + threadIdx.x;
    if (idx >= n * HDIM) return;
    const int m = idx >> 7;
    const int j = idx & 127;
    const int node = s0 + m;
    const int gid = xids[node] * msk[node];
    const float* t = g_tbl + (size_t)gid * 512;
    const float xf = t[384 + j];
    const float c0 = g_c[(size_t)(2 * node + 1) * HDIM + j];
    const float c1 = g_c[(size_t)(2 * node + 2) * HDIM + j];
    const float f0 = sigmf(g_fraw[(size_t)(2 * m) * HDIM + j] + xf);
    const float f1 = sigmf(g_fraw[(size_t)(2 * m + 1) * HDIM + j] + xf);
    const float fc = f0 * c0 + f1 * c1;
    const float iv = g_iouraw[(size_t)m * 384 + j]       + t[j];
    const float ov = g_iouraw[(size_t)m * 384 + 128 + j] + t[128 + j];
    const float uv = g_iouraw[(size_t)m * 384 + 256 + j] + t[256 + j];
    const float cv = sigmf(iv) * tanhf(uv) + fc;
    const float hv = sigmf(ov) * tanhf(cv);
    g_c[(size_t)node * HDIM + j] = cv;
    g_h[(size_t)node * HDIM + j] = hv;
}

// ================= output projection =================
__global__ void out_gemm(const float* __restrict__ Wout,
                         const float* __restrict__ bout,
                         float* __restrict__ out)
{
    __shared__ float Ws[HDIM * 5];
    __shared__ float bs[5];
    const int tid = threadIdx.x;
    for (int i = tid; i < HDIM * 5; i += blockDim.x) Ws[i] = Wout[i];
    if (tid < 5) bs[tid] = bout[tid];
    __syncthreads();

    const int node = (blockIdx.x * blockDim.x + tid) >> 5;
    const int lane = tid & 31;
    if (node >= NNODES) return;

    const float* hp = g_h + (size_t)node * HDIM;
    float p[5] = {0.f, 0.f, 0.f, 0.f, 0.f};
    #pragma unroll
    for (int e = 0; e < 4; e++) {
        const int k = e * 32 + lane;
        const float x = hp[k];
        #pragma unroll
        for (int c = 0; c < 5; c++) p[c] += x * Ws[k * 5 + c];
    }
    #pragma unroll
    for (int off = 16; off > 0; off >>= 1)
        #pragma unroll
        for (int c = 0; c < 5; c++)
            p[c] += __shfl_xor_sync(0xffffffffu, p[c], off);

    if (lane == 0) {
        #pragma unroll
        for (int c = 0; c < 5; c++)
            out[(size_t)node * 5 + c] = p[c] + bs[c];
    }
}

// ================= launch =================
extern "C" void kernel_launch(void* const* d_in, const int* in_sizes, int n_in,
                              void* d_out, int out_size)
{
    const int*   x_ids = (const int*)d_in[0];
    const int*   mask  = (const int*)d_in[1];
    const float* emb   = (const float*)d_in[2];
    const float* W_iou = (const float*)d_in[3];
    const float* U_iou = (const float*)d_in[4];
    const float* b_iou = (const float*)d_in[5];
    const float* W_f   = (const float*)d_in[6];
    const float* U_f   = (const float*)d_in[7];
    const float* b_f   = (const float*)d_in[8];
    const float* W_out = (const float*)d_in[9];
    const float* b_out = (const float*)d_in[10];
    float* out = (float*)d_out;

    cudaFuncSetAttribute(proj_gemm, cudaFuncAttributeMaxDynamicSharedMemorySize, SMEM_DYN);
    cudaFuncSetAttribute(level_gemm, cudaFuncAttributeMaxDynamicSharedMemorySize, SMEM_DYN);

    prep_weights<<<(8 * 128 * 64 + 255) / 256, 256>>>(W_iou, W_f, U_iou, U_f, b_iou, b_f);

    {
        dim3 grid(4, (VOCAB + 127) / 128);
        proj_gemm<<<grid, 256, SMEM_DYN>>>(emb);
    }

    leaf_update<<<(LEAF_N * HDIM + 255) / 256, 256>>>(x_ids, mask);

    for (int d = DEPTH - 2; d >= 0; --d) {
        const int n = 1 << d;
        const int s0 = n - 1;
        dim3 grid(4, (2 * n + 127) / 128);
        level_gemm<<<grid, 256, SMEM_DYN>>>(s0, n);
        level_update<<<(n * HDIM + 255) / 256, 256>>>(x_ids, mask, s0, n);
    }

    out_gemm<<<(NNODES + 7) / 8, 256>>>(W_out, b_out, out);
}